// round 17
// baseline (speedup 1.0000x reference)
#include <cuda_runtime.h>
#include <cuda_fp16.h>
#include <math.h>
#include <stdint.h>

// ---------------------------------------------------------------------------
// Round 17: single-kernel CO-RESIDENT producer/consumer.
// Block = 512 thr: warps 0..11 = MLP (fp16 1-term tensor pipeline, 192-pt
// tile from smem enc buffer), warps 12..15 = gather (depth-2 pipelined,
// x-corner-paired, fills the OTHER enc buffer for this block's next tile).
// Gather binds L1tex wavefronts, MLP binds issue/tensor -> disjoint pipes on
// the same SM; one __syncthreads per tile; no global enc scratch at all.
// ---------------------------------------------------------------------------

#define LVLS 24
#define TSZ  (1u << 19)
#define P1   2654435761u
#define P2   805459861u

#define TILE_PTS  192
#define NTHREADS  512
#define NMLPW     12
#define ENCW      25            // u32 stride per point (odd -> conflict-free)

#define WOFF_L0 0               // 64 x 56 (K=48)
#define WOFF_L1 3584            // 64 x 72
#define WOFF_L2 8192            // 64 x 72
#define WOFF_L3 12800           // 72 x 72 (N 65->72)
#define WOFF_R0 17984           // 64 x 88 (K=80, staged shifted by 1)
#define WOFF_R1 23616           // 64 x 72
#define WOFF_R2 28224           //  8 x 72 (N 3->8)

#define BOFF_L0 0
#define BOFF_L1 64
#define BOFF_L2 128
#define BOFF_L3 192
#define BOFF_R0 264
#define BOFF_R1 328
#define BOFF_R2 392

#define SO_WHI  0                               // 57600 B
#define SO_BIAS 57600                           // 1600 B
#define SO_E0   59200                           // 19200 B
#define SO_E1   78400                           // 19200 B
#define SMEM_BYTES 97600

struct ResArr { float r[LVLS]; };
struct WPtrs  { const float* w[14]; };

typedef unsigned short u16;
typedef unsigned int   u32;

__device__ __forceinline__ float gelu_fast(float x) {
    float x2 = x * x;
    float inner = fmaf(0.044715f * x2, x, x) * 0.7978845608028654f;
    float t;
    asm("tanh.approx.f32 %0, %1;" : "=f"(t) : "f"(inner));
    float hx = 0.5f * x;
    return fmaf(hx, t, hx);
}
__device__ __forceinline__ float softplus_f(float x) {
    return fmaxf(x, 0.0f) + log1pf(expf(-fabsf(x)));
}
__device__ __forceinline__ float sigmoid_f(float x) {
    return 1.0f / (1.0f + expf(-x));
}

#define MMA_F16(d, a0, a1, a2, a3, b0, b1)                                    \
    asm volatile(                                                             \
        "mma.sync.aligned.m16n8k16.row.col.f32.f16.f16.f32 "                  \
        "{%0,%1,%2,%3}, {%4,%5,%6,%7}, {%8,%9}, {%0,%1,%2,%3};"               \
        : "+f"(d[0]), "+f"(d[1]), "+f"(d[2]), "+f"(d[3])                      \
        : "r"(a0), "r"(a1), "r"(a2), "r"(a3), "r"(b0), "r"(b1))

#define LDSM_X4(r0, r1, r2, r3, addr)                                         \
    asm volatile("ldmatrix.sync.aligned.m8n8.x4.shared.b16 {%0,%1,%2,%3}, [%4];" \
        : "=r"(r0), "=r"(r1), "=r"(r2), "=r"(r3) : "r"(addr))

#define LDSM_X2(r0, r1, addr)                                                 \
    asm volatile("ldmatrix.sync.aligned.m8n8.x2.shared.b16 {%0,%1}, [%2];"    \
        : "=r"(r0), "=r"(r1) : "r"(addr))

__device__ __forceinline__ u32 pack_h2(float v0, float v1) {
    u32 h;
    asm("cvt.rn.f16x2.f32 %0, %1, %2;" : "=r"(h) : "f"(v1), "f"(v0));
    return h;
}

template<int KP>
__device__ __forceinline__ u32 lane_adj(int lane) {
    int row8  = lane & 7;
    int which = lane >> 3;
    int n_off = ((which & 2) << 2) + row8;
    int k_off = (which & 1) << 3;
    return (u32)((n_off * KP + k_off) * 2);
}

// 1-term fp16 layer (weights hi-only)
template<int KT, int NT, int KP>
__device__ __forceinline__ void run_layer(const u32* __restrict__ ah,
                                          u32 shi,
                                          const float* __restrict__ bias,
                                          float (&acc)[NT][4], int qm)
{
#pragma unroll
    for (int nt = 0; nt < NT; nt++) {
        float b0 = bias[nt * 8 + 2 * qm];
        float b1 = bias[nt * 8 + 2 * qm + 1];
        acc[nt][0] = b0; acc[nt][1] = b1;
        acc[nt][2] = b0; acc[nt][3] = b1;
    }
#pragma unroll
    for (int kt = 0; kt < KT; kt++) {
#pragma unroll
        for (int p = 0; p < NT / 2; p++) {
            u32 off = (u32)((p * 16 * KP + kt * 16) * 2);
            u32 bh0, bh1, bh2, bh3;
            LDSM_X4(bh0, bh1, bh2, bh3, shi + off);
            MMA_F16(acc[2*p],   ah[4*kt], ah[4*kt+1], ah[4*kt+2], ah[4*kt+3], bh0, bh1);
            MMA_F16(acc[2*p+1], ah[4*kt], ah[4*kt+1], ah[4*kt+2], ah[4*kt+3], bh2, bh3);
        }
        if (NT & 1) {
            u32 off = (u32)(((NT - 1) * 8 * KP + kt * 16) * 2);
            u32 bh0, bh1;
            LDSM_X2(bh0, bh1, shi + off);
            MMA_F16(acc[NT-1], ah[4*kt], ah[4*kt+1], ah[4*kt+2], ah[4*kt+3], bh0, bh1);
        }
    }
}

template<int KTN>
__device__ __forceinline__ void frags_gelu(const float (*acc)[4], u32* ah)
{
#pragma unroll
    for (int kt = 0; kt < KTN; kt++) {
        ah[4*kt+0] = pack_h2(gelu_fast(acc[2*kt][0]),   gelu_fast(acc[2*kt][1]));
        ah[4*kt+1] = pack_h2(gelu_fast(acc[2*kt][2]),   gelu_fast(acc[2*kt][3]));
        ah[4*kt+2] = pack_h2(gelu_fast(acc[2*kt+1][0]), gelu_fast(acc[2*kt+1][1]));
        ah[4*kt+3] = pack_h2(gelu_fast(acc[2*kt+1][2]), gelu_fast(acc[2*kt+1][3]));
    }
}

// ---- producer unit state (depth-2) ----
struct PU {
    float2 f[8];
    float wx, wy, wz;
    int dst;                    // u32 offset within enc buffer
};

__device__ __forceinline__ void p_issue(const float* __restrict__ pts,
                                        const float* __restrict__ table,
                                        const ResArr& res, int base_pt,
                                        int n, int u, PU& s)
{
    int l  = u / TILE_PTS;
    int pl = u - l * TILE_PTS;
    int p  = base_pt + pl;
    if (p >= n) p = n - 1;      // clamp: writes land in unused buffer rows
    s.dst = pl * ENCW + l;

    float x0 = (pts[p * 3 + 0] + 1.0f) * 0.5f;
    float y0 = (pts[p * 3 + 1] + 1.0f) * 0.5f;
    float z0 = (pts[p * 3 + 2] + 1.0f) * 0.5f;
    float rl = res.r[l];
    float posx = x0 * rl, posy = y0 * rl, posz = z0 * rl;
    float fx = floorf(posx), fy = floorf(posy), fz = floorf(posz);
    s.wx = posx - fx; s.wy = posy - fy; s.wz = posz - fz;
    unsigned ux = (unsigned)fx, uy = (unsigned)fy, uz = (unsigned)fz;
    unsigned hY[2] = {uy * P1, (uy + 1u) * P1};
    unsigned hZ[2] = {uz * P2, (uz + 1u) * P2};
    const float2* tb = (const float2*)table + (size_t)l * TSZ;

    if ((ux & 1u) == 0u) {
        const float4* tb4 = (const float4*)tb;
#pragma unroll
        for (int by = 0; by < 2; by++) {
#pragma unroll
            for (int bz = 0; bz < 2; bz++) {
                unsigned E = (ux ^ hY[by] ^ hZ[bz]) & (TSZ - 1u);
                float4 q = __ldg(tb4 + (E >> 1));
                float2 e0 = make_float2(q.x, q.y);
                float2 e1 = make_float2(q.z, q.w);
                bool odd = (E & 1u) != 0u;
                s.f[(0 << 2) | (by << 1) | bz] = odd ? e1 : e0;
                s.f[(1 << 2) | (by << 1) | bz] = odd ? e0 : e1;
            }
        }
    } else {
        unsigned hX[2] = {ux, ux + 1u};
#pragma unroll
        for (int c = 0; c < 8; c++) {
            int bx = (c >> 2) & 1, by = (c >> 1) & 1, bz = c & 1;
            unsigned idx = (hX[bx] ^ hY[by] ^ hZ[bz]) & (TSZ - 1u);
            s.f[c] = __ldg(tb + idx);
        }
    }
}

__device__ __forceinline__ void p_consume(PU& s, u32* __restrict__ buf)
{
    float wX[2] = {1.0f - s.wx, s.wx};
    float wY[2] = {1.0f - s.wy, s.wy};
    float wZ[2] = {1.0f - s.wz, s.wz};
    float a0 = 0.0f, a1 = 0.0f;
#pragma unroll
    for (int c = 0; c < 8; c++) {
        int bx = (c >> 2) & 1, by = (c >> 1) & 1, bz = c & 1;
        float wt = wX[bx] * wY[by] * wZ[bz];
        a0 = fmaf(s.f[c].x, wt, a0);
        a1 = fmaf(s.f[c].y, wt, a1);
    }
    buf[s.dst] = pack_h2(a0, a1);
}

// fill one tile's enc buffer (gather warps: 128 threads, 36 units each)
__device__ void fill_tile(const float* __restrict__ pts,
                          const float* __restrict__ table,
                          const ResArr& res, u32* __restrict__ buf,
                          int base_pt, int n, int gwtid)
{
    PU A, B;
    p_issue(pts, table, res, base_pt, n, gwtid, A);
    p_issue(pts, table, res, base_pt, n, gwtid + 128, B);
#pragma unroll 1
    for (int i = 0; i < 36; i++) {
        PU& cur = (i & 1) ? B : A;
        p_consume(cur, buf);
        if (i + 2 < 36)
            p_issue(pts, table, res, base_pt, n, gwtid + (i + 2) * 128, cur);
    }
}

// ---- staging ----
__device__ void stage_w(const float* __restrict__ g, u16* hi,
                        int realK, int realN, int K, int NPAD, int KP, int tid)
{
    for (int idx = tid; idx < NPAD * K; idx += NTHREADS) {
        int nn = idx / K, kk = idx % K;
        float v = (kk < realK && nn < realN) ? g[kk * realN + nn] : 0.0f;
        hi[nn * KP + kk] = __half_as_ushort(__float2half_rn(v));
    }
}
__device__ void stage_w_shift(const float* __restrict__ g, u16* hi, int tid)
{
    const int K = 80, KP = 88;
    for (int idx = tid; idx < 64 * K; idx += NTHREADS) {
        int nn = idx / K, kk = idx % K;
        float v = (kk >= 1 && kk <= 73) ? g[(kk - 1) * 64 + nn] : 0.0f;
        hi[nn * KP + kk] = __half_as_ushort(__float2half_rn(v));
    }
}
__device__ void stage_b(const float* __restrict__ g, float* dst,
                        int realN, int NPAD, int tid)
{
    for (int i = tid; i < NPAD; i += NTHREADS)
        dst[i] = (i < realN) ? g[i] : 0.0f;
}

__global__ void __launch_bounds__(NTHREADS, 1)
nerf_fused(const float* __restrict__ pts,
           const float* __restrict__ dirs,
           const float* __restrict__ table,
           WPtrs prm, ResArr res,
           float* __restrict__ out, int n)
{
    extern __shared__ char smem[];
    u16*   whi  = (u16*)(smem + SO_WHI);
    float* bias = (float*)(smem + SO_BIAS);
    u32*   enc0 = (u32*)(smem + SO_E0);
    u32*   enc1 = (u32*)(smem + SO_E1);

    const int tid  = threadIdx.x;
    const int warp = tid >> 5;
    const int lane = tid & 31;
    const int qr = lane >> 2, qm = lane & 3;

    stage_w(prm.w[0],  whi + WOFF_L0, 48, 64, 48, 64, 56, tid);
    stage_w(prm.w[2],  whi + WOFF_L1, 64, 64, 64, 64, 72, tid);
    stage_w(prm.w[4],  whi + WOFF_L2, 64, 64, 64, 64, 72, tid);
    stage_w(prm.w[6],  whi + WOFF_L3, 64, 65, 64, 72, 72, tid);
    stage_w_shift(prm.w[8], whi + WOFF_R0, tid);
    stage_w(prm.w[10], whi + WOFF_R1, 64, 64, 64, 64, 72, tid);
    stage_w(prm.w[12], whi + WOFF_R2, 64,  3, 64,  8, 72, tid);
    stage_b(prm.w[1],  bias + BOFF_L0, 64, 64, tid);
    stage_b(prm.w[3],  bias + BOFF_L1, 64, 64, tid);
    stage_b(prm.w[5],  bias + BOFF_L2, 64, 64, tid);
    stage_b(prm.w[7],  bias + BOFF_L3, 65, 72, tid);
    stage_b(prm.w[9],  bias + BOFF_R0, 64, 64, tid);
    stage_b(prm.w[11], bias + BOFF_R1, 64, 64, tid);
    stage_b(prm.w[13], bias + BOFF_R2,  3,  8, tid);
    __syncthreads();

    const int ntiles = (n + TILE_PTS - 1) / TILE_PTS;
    int tile = blockIdx.x;
    if (tile >= ntiles) return;

    const bool mlp_role = (warp < NMLPW);
    const int  rg = warp;                       // MLP row-group
    const int  gwtid = tid - NMLPW * 32;        // gather lane 0..127

    const u32 whi_s = (u32)__cvta_generic_to_shared(whi);
    const u32 adj56 = lane_adj<56>(lane);
    const u32 adj72 = lane_adj<72>(lane);
    const u32 adj88 = lane_adj<88>(lane);
    const u32 sL0h = whi_s + WOFF_L0*2 + adj56;
    const u32 sL1h = whi_s + WOFF_L1*2 + adj72;
    const u32 sL2h = whi_s + WOFF_L2*2 + adj72;
    const u32 sL3h = whi_s + WOFF_L3*2 + adj72;
    const u32 sR0h = whi_s + WOFF_R0*2 + adj88;
    const u32 sR1h = whi_s + WOFF_R1*2 + adj72;
    const u32 sR2h = whi_s + WOFF_R2*2 + adj72;

    // prologue: gather warps fill enc0 for the first tile
    if (!mlp_role)
        fill_tile(pts, table, res, enc0, tile * TILE_PTS, n, gwtid);
    __syncthreads();

    int k = 0;
    while (true) {
        const int base = tile * TILE_PTS;
        const int next = tile + gridDim.x;
        const bool g = (next < ntiles);

        if (!mlp_role) {
            if (g)
                fill_tile(pts, table, res, (k & 1) ? enc0 : enc1,
                          next * TILE_PTS, n, gwtid);
        } else {
            const u32* buf = (k & 1) ? enc1 : enc0;
            u32 ah[20];
            float dxA, dyA, dzA, dxB, dyB, dzB;
            {
                const u32* e0 = buf + (rg * 16 + qr) * ENCW;
                const u32* e1 = e0 + 8 * ENCW;
#pragma unroll
                for (int kt = 0; kt < 3; kt++) {
                    ah[4*kt+0] = e0[qm + 8 * kt];
                    ah[4*kt+1] = e1[qm + 8 * kt];
                    ah[4*kt+2] = e0[qm + 8 * kt + 4];
                    ah[4*kt+3] = e1[qm + 8 * kt + 4];
                }
                int pA = base + rg * 16 + qr;
                int pB = pA + 8;
                int gA = (pA < n) ? pA : n - 1;
                int gB = (pB < n) ? pB : n - 1;
                dxA = __ldg(dirs + gA * 3 + 0);
                dyA = __ldg(dirs + gA * 3 + 1);
                dzA = __ldg(dirs + gA * 3 + 2);
                dxB = __ldg(dirs + gB * 3 + 0);
                dyB = __ldg(dirs + gB * 3 + 1);
                dzB = __ldg(dirs + gB * 3 + 2);
            }

            float acc[8][4];
            run_layer<3, 8, 56>(ah, sL0h, bias + BOFF_L0, acc, qm);
            frags_gelu<4>(acc, ah);
            run_layer<4, 8, 72>(ah, sL1h, bias + BOFF_L1, acc, qm);
            frags_gelu<4>(acc, ah);
            run_layer<4, 8, 72>(ah, sL2h, bias + BOFF_L2, acc, qm);
            frags_gelu<4>(acc, ah);
            float acc9[9][4];
            run_layer<4, 9, 72>(ah, sL3h, bias + BOFF_L3, acc9, qm);

            if (qm == 0) {
                int pA = base + rg * 16 + qr;
                int pB = pA + 8;
                if (pA < n) out[(size_t)3 * n + pA] = softplus_f(acc9[0][0]);
                if (pB < n) out[(size_t)3 * n + pB] = softplus_f(acc9[0][2]);
            }

            float shA[9], shB[9];
            shA[0] = 0.28209479177387814f;
            shA[1] = -0.48860251190291987f * dyA;
            shA[2] =  0.48860251190291987f * dzA;
            shA[3] = -0.48860251190291987f * dxA;
            shA[4] =  1.0925484305920792f  * dxA * dyA;
            shA[5] = -1.0925484305920792f  * dyA * dzA;
            shA[6] =  0.31539156525252005f * (3.0f * dzA * dzA - 1.0f);
            shA[7] = -1.0925484305920792f  * dxA * dzA;
            shA[8] =  0.5462742152960396f  * (dxA * dxA - dyA * dyA);
            shB[0] = 0.28209479177387814f;
            shB[1] = -0.48860251190291987f * dyB;
            shB[2] =  0.48860251190291987f * dzB;
            shB[3] = -0.48860251190291987f * dxB;
            shB[4] =  1.0925484305920792f  * dxB * dyB;
            shB[5] = -1.0925484305920792f  * dyB * dzB;
            shB[6] =  0.31539156525252005f * (3.0f * dzB * dzB - 1.0f);
            shB[7] = -1.0925484305920792f  * dxB * dzB;
            shB[8] =  0.5462742152960396f  * (dxB * dxB - dyB * dyB);

            frags_gelu<4>(acc9, ah);
            {
                float e64A = gelu_fast(acc9[8][0]);
                float e64B = gelu_fast(acc9[8][2]);
                float v0A, v1A, v2A, v3A, v0B, v1B, v2B, v3B;
                if (qm == 0) {
                    v0A = e64A;   v1A = shA[0]; v2A = shA[7]; v3A = shA[8];
                    v0B = e64B;   v1B = shB[0]; v2B = shB[7]; v3B = shB[8];
                } else if (qm == 1) {
                    v0A = shA[1]; v1A = shA[2]; v2A = 0.0f;   v3A = 0.0f;
                    v0B = shB[1]; v1B = shB[2]; v2B = 0.0f;   v3B = 0.0f;
                } else if (qm == 2) {
                    v0A = shA[3]; v1A = shA[4]; v2A = 0.0f;   v3A = 0.0f;
                    v0B = shB[3]; v1B = shB[4]; v2B = 0.0f;   v3B = 0.0f;
                } else {
                    v0A = shA[5]; v1A = shA[6]; v2A = 0.0f;   v3A = 0.0f;
                    v0B = shB[5]; v1B = shB[6]; v2B = 0.0f;   v3B = 0.0f;
                }
                ah[16] = pack_h2(v0A, v1A);
                ah[17] = pack_h2(v0B, v1B);
                ah[18] = pack_h2(v2A, v3A);
                ah[19] = pack_h2(v2B, v3B);
            }

            run_layer<5, 8, 88>(ah, sR0h, bias + BOFF_R0, acc, qm);
            frags_gelu<4>(acc, ah);
            run_layer<4, 8, 72>(ah, sR1h, bias + BOFF_R1, acc, qm);
            frags_gelu<4>(acc, ah);
            {
                float acc1[1][4];
                run_layer<4, 1, 72>(ah, sR2h, bias + BOFF_R2, acc1, qm);
                int pt0 = base + rg * 16 + qr;
                int pt1 = pt0 + 8;
                if (qm == 0) {
                    if (pt0 < n) {
                        out[pt0 * 3 + 0] = sigmoid_f(acc1[0][0]);
                        out[pt0 * 3 + 1] = sigmoid_f(acc1[0][1]);
                    }
                    if (pt1 < n) {
                        out[pt1 * 3 + 0] = sigmoid_f(acc1[0][2]);
                        out[pt1 * 3 + 1] = sigmoid_f(acc1[0][3]);
                    }
                } else if (qm == 1) {
                    if (pt0 < n) out[pt0 * 3 + 2] = sigmoid_f(acc1[0][0]);
                    if (pt1 < n) out[pt1 * 3 + 2] = sigmoid_f(acc1[0][2]);
                }
            }
        }

        __syncthreads();
        if (!g) break;
        tile = next;
        k ^= 1;
    }
}

extern "C" void kernel_launch(void* const* d_in, const int* in_sizes, int n_in,
                              void* d_out, int out_size)
{
    const float* pts   = (const float*)d_in[0];
    const float* dirs  = (const float*)d_in[1];
    const float* table = (const float*)d_in[2];

    WPtrs prm;
    for (int a = 0; a < 14; a++) prm.w[a] = (const float*)d_in[3 + a];

    int n = in_sizes[0] / 3;

    ResArr res;
    double b = exp((log(2048.0) - log(16.0)) / 23.0);
    for (int l = 0; l < LVLS; l++)
        res.r[l] = (float)floor(16.0 * pow(b, (double)l));

    cudaFuncSetAttribute(nerf_fused,
                         cudaFuncAttributeMaxDynamicSharedMemorySize,
                         SMEM_BYTES);

    int dev = 0, sms = 148;
    cudaGetDevice(&dev);
    cudaDeviceGetAttribute(&sms, cudaDevAttrMultiProcessorCount, dev);
    int ntiles = (n + TILE_PTS - 1) / TILE_PTS;
    int blocks = (sms < ntiles) ? sms : ntiles;

    nerf_fused<<<blocks, NTHREADS, SMEM_BYTES>>>(
        pts, dirs, table, prm, res, (float*)d_out, n);
}